// round 1
// baseline (speedup 1.0000x reference)
#include <cuda_runtime.h>
#include <cuda_bf16.h>
#include <cstdint>

// MX quantize-dequantize, block=32 along rows (rows are contiguous, so blocks
// are 32 consecutive floats). One thread owns one 32-block: 8x float4 load,
// amax reduce in registers, bf16-exact scale, quantize, 8x float4 store.

__device__ __forceinline__ float quant1(float x, float inv_s, float s) {
    // a = x / s  (emulated by correctly-rounded reciprocal multiply)
    float a = x * inv_s;
    float aa = fabsf(a);
    // e = floor(log2(|a|)) via exponent field; clamp to -6 (e4m3 min exp)
    uint32_t eb = (__float_as_uint(aa) >> 23);          // |a| -> no sign bit
    eb = eb < 121u ? 121u : eb;                         // e >= -6  (121 = 127-6)
    // Round |a| to nearest multiple of 2^(e-3) (4 fractional mantissa bits):
    // big = 2^(e+20), ulp(big) = 2^(e-3). (|a|+big)-big is exact.
    float big = __uint_as_float((eb + 20u) << 23);
    float r = (aa + big) - big;
    // saturate to e4m3 max_norm, restore sign, dequantize
    r = fminf(r, 448.0f);
    return copysignf(r, a) * s;
}

__global__ __launch_bounds__(256) void mxq_kernel(const float4* __restrict__ in,
                                                  float4* __restrict__ out,
                                                  int nblk) {
    int b = blockIdx.x * blockDim.x + threadIdx.x;
    if (b >= nblk) return;

    const float4* p = in + (size_t)b * 8;
    float4 v[8];
#pragma unroll
    for (int i = 0; i < 8; i++) v[i] = __ldcs(p + i);   // streaming loads, MLP=8

    // per-block amax
    float amax = 0.0f;
#pragma unroll
    for (int i = 0; i < 8; i++) {
        amax = fmaxf(amax, fabsf(v[i].x));
        amax = fmaxf(amax, fabsf(v[i].y));
        amax = fmaxf(amax, fabsf(v[i].z));
        amax = fmaxf(amax, fabsf(v[i].w));
    }

    // scale = bf16(amax / 448); nano-mantissa rounding performed in bf16:
    //   s = floor_bf16(bf16(s*256 + 0.5)) / 256 ;  s==0 -> 1
    // All steps reproduced exactly: *256 and /256 are exact pow2 scalings of a
    // bf16 value; fp32 add then RN-to-bf16 == bf16 RN add; floor of a bf16
    // value is exact in fp32.
    float sc = __bfloat162float(__float2bfloat16(amax * (1.0f / 448.0f)));
    float t  = sc * 256.0f;
    float u  = __bfloat162float(__float2bfloat16(t + 0.5f));
    float s  = floorf(u) * (1.0f / 256.0f);
    if (s == 0.0f) s = 1.0f;
    float inv_s = __frcp_rn(s);

#pragma unroll
    for (int i = 0; i < 8; i++) {
        v[i].x = quant1(v[i].x, inv_s, s);
        v[i].y = quant1(v[i].y, inv_s, s);
        v[i].z = quant1(v[i].z, inv_s, s);
        v[i].w = quant1(v[i].w, inv_s, s);
    }

    float4* q = out + (size_t)b * 8;
#pragma unroll
    for (int i = 0; i < 8; i++) __stcs(q + i, v[i]);    // streaming stores
}

extern "C" void kernel_launch(void* const* d_in, const int* in_sizes, int n_in,
                              void* d_out, int out_size) {
    const float* x = (const float*)d_in[0];
    float* y = (float*)d_out;
    int n = in_sizes[0];          // 8192*8192 = 67108864, multiple of 32
    int nblk = n / 32;            // 2097152 blocks-of-32, one thread each
    int threads = 256;
    int blocks = (nblk + threads - 1) / threads;
    mxq_kernel<<<blocks, threads>>>((const float4*)x, (float4*)y, nblk);
}

// round 2
// speedup vs baseline: 1.6021x; 1.6021x over previous
#include <cuda_runtime.h>
#include <cuda_bf16.h>
#include <cstdint>

// MX quantize-dequantize, block=32 contiguous floats.
// Warp-cooperative: each thread owns one float4; a 32-float block = 8 adjacent
// lanes. Block amax via 3 butterfly shuffles within 8-lane groups. Each thread
// processes 2 float4s (two coalesced warp-tiles) for MLP=2.

__device__ __forceinline__ float quant1(float x, float inv_s, float s) {
    float a = x * inv_s;                                // x / s (rcp multiply)
    float aa = fabsf(a);
    uint32_t eb = (__float_as_uint(aa) >> 23);          // floor(log2|a|) + 127
    eb = eb < 121u ? 121u : eb;                         // clamp e >= -6
    // round |a| to nearest multiple of 2^(e-3): add/sub 2^(e+20)
    float big = __uint_as_float((eb + 20u) << 23);
    float r = (aa + big) - big;
    r = fminf(r, 448.0f);                               // e4m3 max_norm
    return copysignf(r, a) * s;
}

__device__ __forceinline__ float block_scale(float amax) {
    // bf16-exact: s = floor(bf16(bf16(amax/448)*256 + 0.5))/256 ; 0 -> 1
    float sc = __bfloat162float(__float2bfloat16(amax * (1.0f / 448.0f)));
    float u  = __bfloat162float(__float2bfloat16(sc * 256.0f + 0.5f));
    float s  = floorf(u) * (1.0f / 256.0f);
    return (s == 0.0f) ? 1.0f : s;
}

__device__ __forceinline__ void process4(float4& v, float4* out, int idx) {
    float amax = fmaxf(fmaxf(fabsf(v.x), fabsf(v.y)),
                       fmaxf(fabsf(v.z), fabsf(v.w)));
    // reduce amax across the 8 lanes owning this 32-block
    amax = fmaxf(amax, __shfl_xor_sync(0xffffffffu, amax, 1));
    amax = fmaxf(amax, __shfl_xor_sync(0xffffffffu, amax, 2));
    amax = fmaxf(amax, __shfl_xor_sync(0xffffffffu, amax, 4));

    float s = block_scale(amax);
    float inv_s = __frcp_rn(s);

    v.x = quant1(v.x, inv_s, s);
    v.y = quant1(v.y, inv_s, s);
    v.z = quant1(v.z, inv_s, s);
    v.w = quant1(v.w, inv_s, s);
    __stcs(out + idx, v);
}

__global__ __launch_bounds__(256) void mxq_kernel(const float4* __restrict__ in,
                                                  float4* __restrict__ out,
                                                  int n4) {
    int i0 = blockIdx.x * (blockDim.x * 2) + threadIdx.x;   // tile 0
    int i1 = i0 + blockDim.x;                               // tile 1

    bool ok0 = i0 < n4;
    bool ok1 = i1 < n4;
    float4 v0, v1;
    if (ok0) v0 = __ldcs(in + i0);                          // coalesced, MLP=2
    if (ok1) v1 = __ldcs(in + i1);

    // grids here are exact multiples; guards are for safety only, and all
    // lanes of an 8-group share the same predicate (i multiples of 8).
    if (ok0) process4(v0, out, i0);
    if (ok1) process4(v1, out, i1);
}

extern "C" void kernel_launch(void* const* d_in, const int* in_sizes, int n_in,
                              void* d_out, int out_size) {
    const float* x = (const float*)d_in[0];
    float* y = (float*)d_out;
    int n = in_sizes[0];              // 8192*8192
    int n4 = n / 4;                   // float4 count (16,777,216)
    int threads = 256;
    int per_block = threads * 2;      // 2 float4 per thread
    int blocks = (n4 + per_block - 1) / per_block;
    mxq_kernel<<<blocks, threads>>>((const float4*)x, (float4*)y, n4);
}